// round 1
// baseline (speedup 1.0000x reference)
#include <cuda_runtime.h>
#include <math.h>

// Problem constants
#define BB   1024
#define DM   512
#define NH   8
#define HD   64
#define NN   81     // 9x9 tokens
#define OC   1536   // 3*DM

// 510 MB scratch for qkv projection result, layout [B][1536][81]
__device__ float g_qkv[(size_t)BB * OC * NN];

// ---------------------------------------------------------------------------
// Kernel 1: QKV projection GEMM
//   qkv[b][o][n] = sum_c W[o][c] * x[b][c][n] + bias[o]
// Block: 64 o-rows x 81 n-cols, K tiled by 32. 256 threads, 4x6 micro-tile.
// ---------------------------------------------------------------------------
__global__ __launch_bounds__(256) void qkv_gemm(const float* __restrict__ x,
                                                const float* __restrict__ w,
                                                const float* __restrict__ bias) {
    const int b  = blockIdx.y;
    const int o0 = blockIdx.x * 64;

    __shared__ float Ws[32][65];   // [k][o], padded
    __shared__ float Xs[32][96];   // [k][n], padded to 96 (n tail zeroed)

    const int tid = threadIdx.x;
    const int tx  = tid & 15;      // n direction
    const int ty  = tid >> 4;      // o direction

    float acc[4][6];
#pragma unroll
    for (int i = 0; i < 4; i++)
#pragma unroll
        for (int j = 0; j < 6; j++) acc[i][j] = 0.0f;

    const float* xb = x + (size_t)b * DM * NN;

    for (int k0 = 0; k0 < DM; k0 += 32) {
        // Load W tile 64x32 (coalesced over c)
        for (int idx = tid; idx < 64 * 32; idx += 256) {
            int o = idx >> 5;
            int c = idx & 31;
            Ws[c][o] = w[(size_t)(o0 + o) * DM + k0 + c];
        }
        // Load X tile 32x81 (coalesced over n), zero pad tail
        for (int idx = tid; idx < 32 * 96; idx += 256) {
            int c = idx / 96;
            int n = idx % 96;
            Xs[c][n] = (n < NN) ? xb[(size_t)(k0 + c) * NN + n] : 0.0f;
        }
        __syncthreads();

#pragma unroll
        for (int kk = 0; kk < 32; kk++) {
            float wv[4], xv[6];
#pragma unroll
            for (int i = 0; i < 4; i++) wv[i] = Ws[kk][ty * 4 + i];
#pragma unroll
            for (int j = 0; j < 6; j++) xv[j] = Xs[kk][tx + 16 * j];
#pragma unroll
            for (int i = 0; i < 4; i++)
#pragma unroll
                for (int j = 0; j < 6; j++) acc[i][j] += wv[i] * xv[j];
        }
        __syncthreads();
    }

    // Epilogue: add bias, write to scratch
#pragma unroll
    for (int i = 0; i < 4; i++) {
        const int o = o0 + ty * 4 + i;
        const float bv = bias[o];
        float* dst = g_qkv + ((size_t)b * OC + o) * NN;
#pragma unroll
        for (int j = 0; j < 6; j++) {
            const int n = tx + 16 * j;
            if (n < NN) dst[n] = acc[i][j] + bv;
        }
    }
}

// ---------------------------------------------------------------------------
// Kernel 2: attention per (b, h).
//   Keff[m][d] = K[m][d] + rel_h[h][d][m%9] + rel_w[h][d][m/9]
//   S[n][m] = Q[n] . Keff[m]   (fuses content_content + content_position)
//   P = softmax_m(S); out[n][d] = sum_m P[n][m] * V[m][d]
// smem: Qs[81][65] + Ks[81][65] (reused for V) + S[81][83]  = 69,012 B
// ---------------------------------------------------------------------------
#define QP 65
#define SP 83
__global__ __launch_bounds__(256) void attn_kernel(const float* __restrict__ rel_h,
                                                   const float* __restrict__ rel_w,
                                                   float* __restrict__ out) {
    extern __shared__ float sm[];
    float* Qs = sm;                    // [81][65]
    float* Ks = sm + NN * QP;          // [81][65], later reused as V
    float* S  = sm + 2 * NN * QP;      // [81][83]

    const int bh = blockIdx.x;
    const int b  = bh >> 3;
    const int h  = bh & 7;
    const int tid = threadIdx.x;

    const float* qkvb = g_qkv + (size_t)b * OC * NN;
    const float* Qg = qkvb + (size_t)(h * HD) * NN;
    const float* Kg = qkvb + (size_t)(DM + h * HD) * NN;
    const float* Vg = qkvb + (size_t)(2 * DM + h * HD) * NN;

    // Load Q (transpose to [n][d]) and Keff
    for (int idx = tid; idx < HD * NN; idx += 256) {
        int d = idx / NN;
        int n = idx % NN;
        Qs[n * QP + d] = Qg[d * NN + n];
        float rh = rel_h[(h * HD + d) * 9 + (n % 9)];
        float rw = rel_w[(h * HD + d) * 9 + (n / 9)];
        Ks[n * QP + d] = Kg[d * NN + n] + rh + rw;
    }
    __syncthreads();

    // Scores: 81x81, dot over 64
    for (int idx = tid; idx < NN * NN; idx += 256) {
        int n = idx / NN;
        int m = idx % NN;
        const float* qp = Qs + n * QP;
        const float* kp = Ks + m * QP;
        float s = 0.0f;
#pragma unroll
        for (int d = 0; d < HD; d++) s += qp[d] * kp[d];
        S[n * SP + m] = s;
    }
    __syncthreads();

    // Load V over Ks (independent of S), softmax rows of S in-place
    for (int idx = tid; idx < HD * NN; idx += 256) {
        int d = idx / NN;
        int n = idx % NN;
        Ks[n * QP + d] = Vg[d * NN + n];
    }
    if (tid < NN) {
        float* row = S + tid * SP;
        float mx = row[0];
        for (int m = 1; m < NN; m++) mx = fmaxf(mx, row[m]);
        float sum = 0.0f;
        for (int m = 0; m < NN; m++) {
            float e = __expf(row[m] - mx);
            row[m] = e;
            sum += e;
        }
        float inv = 1.0f / sum;
        for (int m = 0; m < NN; m++) row[m] *= inv;
    }
    __syncthreads();

    // out[n][d] = sum_m P[n][m] * V[m][d]; write as [b][h*64+d][n] (coalesced in n)
    for (int idx = tid; idx < HD * NN; idx += 256) {
        int d = idx / NN;
        int n = idx % NN;
        const float* pr = S + n * SP;
        float acc = 0.0f;
#pragma unroll
        for (int m = 0; m < NN; m++) acc += pr[m] * Ks[m * QP + d];
        out[((size_t)b * DM + h * HD + d) * NN + n] = acc;
    }
}

// ---------------------------------------------------------------------------
extern "C" void kernel_launch(void* const* d_in, const int* in_sizes, int n_in,
                              void* d_out, int out_size) {
    const float* x     = (const float*)d_in[0];
    const float* qkv_w = (const float*)d_in[1];
    const float* qkv_b = (const float*)d_in[2];
    const float* rel_h = (const float*)d_in[3];
    const float* rel_w = (const float*)d_in[4];
    float* out = (float*)d_out;

    // idempotent; executes immediately even during capture, and the attribute
    // persists from the (non-captured) correctness call onward
    static const int SMEM_ATTN = (2 * NN * QP + NN * SP) * sizeof(float);
    cudaFuncSetAttribute(attn_kernel, cudaFuncAttributeMaxDynamicSharedMemorySize, SMEM_ATTN);

    dim3 g1(OC / 64, BB);
    qkv_gemm<<<g1, 256>>>(x, qkv_w, qkv_b);
    attn_kernel<<<BB * NH, 256, SMEM_ATTN>>>(rel_h, rel_w, out);
}